// round 1
// baseline (speedup 1.0000x reference)
#include <cuda_runtime.h>
#include <math.h>

// Problem constants
constexpr int Bn = 4, CINc = 64, COUTc = 128, Hh = 32, Wwc = 32;
constexpr int NRES = Bn * CINc * Hh * Wwc;      // 262144 (r-space size)
constexpr int NY   = Bn * COUTc * Hh * Wwc;     // 524288
constexpr int NT   = Bn * COUTc * 34 * 34;      // padded intermediate
constexpr int NDOTCTA = 128;
constexpr double LRD = 0.001;

// Scratch (static device arrays: no allocation allowed)
__device__ float g_y0[NY];
__device__ float g_r0[NRES];
__device__ float g_t[NT];
__device__ float g_m1[NRES];
__device__ float g_m2[NRES];
__device__ float g_m3[NRES];
__device__ float g_s[NRES];
__device__ double g_part[NDOTCTA * 10];
__device__ float g_w[4];

// ---------------------------------------------------------------------------
// Generic direct 3x3 conv (cross-correlation) with compile-time variants.
// out[n, oc, i, j] = sum_{ic,u,v} w(oc,ic,u,v) * in[n, ic, i+OFF+u, j+OFF+v]
// WM: 0 -> wgt[oc][ic][u][v]
//     1 -> wgt[ic][oc][u][v]        (transposed channel roles)
//     2 -> wgt[oc][ic][2-u][2-v]    (spatially flipped)
// EPI: 0 -> store acc
//      1 -> relu(acc)
//      2 -> aux[idx] - acc                       (r0 = x - pred)
//      3 -> aux[idx] + acc + 1x1bypass(aux2,wb)  (final output)
// Each thread computes a 4-row vertical strip of one column for OCB channels.
// ---------------------------------------------------------------------------
template<int IC, int OC, int IH, int IW, int OH, int OW, int OFF, int WM,
         int EPI, int OCB, int SPL, int THREADS>
__global__ __launch_bounds__(THREADS)
void conv3(const float* __restrict__ in, const float* __restrict__ wgt,
           const float* __restrict__ aux, const float* __restrict__ aux2,
           const float* __restrict__ wb, float* __restrict__ out)
{
    __shared__ float wsm[OCB * IC * 9];
    const int ocblk = blockIdx.x;
    const int n     = blockIdx.y;
    const int sp    = blockIdx.z;
    const int tid   = threadIdx.x;

    // Stage this block's weight slice into smem, layout wsm[ic][uv][o]
    for (int idx = tid; idx < OCB * IC * 9; idx += THREADS) {
        int o  = idx % OCB;
        int uv = (idx / OCB) % 9;
        int ic = idx / (9 * OCB);
        int u = uv / 3, v = uv % 3;
        int og = ocblk * OCB + o;
        int src;
        if (WM == 0)      src = ((og * IC + ic) * 3 + u) * 3 + v;
        else if (WM == 1) src = ((ic * OC + og) * 3 + u) * 3 + v;
        else              src = ((og * IC + ic) * 3 + (2 - u)) * 3 + (2 - v);
        wsm[idx] = wgt[src];
    }
    __syncthreads();

    constexpr int ROWS   = OH / SPL;
    constexpr int NSTRIP = (ROWS + 3) / 4;
    const int row_base0 = sp * ROWS;

    for (int witem = tid; witem < OW * NSTRIP; witem += THREADS) {
        int col   = witem % OW;
        int strip = witem / OW;
        int row0  = row_base0 + strip * 4;

        float acc[OCB][4];
        #pragma unroll
        for (int o = 0; o < OCB; o++)
            #pragma unroll
            for (int k = 0; k < 4; k++) acc[o][k] = 0.f;

        int  rix[6]; bool rok[6];
        #pragma unroll
        for (int rr = 0; rr < 6; rr++) {
            int r = row0 + OFF + rr;
            rok[rr] = (r >= 0 && r < IH);
            rix[rr] = (rok[rr] ? r : 0) * IW;
        }
        int  cix[3]; bool cok[3];
        #pragma unroll
        for (int cc = 0; cc < 3; cc++) {
            int c = col + OFF + cc;
            cok[cc] = (c >= 0 && c < IW);
            cix[cc] = cok[cc] ? c : 0;
        }

        const float* inb = in + (size_t)n * IC * IH * IW;
        #pragma unroll 2
        for (int ic = 0; ic < IC; ic++) {
            float v[6][3];
            #pragma unroll
            for (int rr = 0; rr < 6; rr++)
                #pragma unroll
                for (int cc = 0; cc < 3; cc++)
                    v[rr][cc] = (rok[rr] && cok[cc]) ? __ldg(inb + rix[rr] + cix[cc]) : 0.f;
            #pragma unroll
            for (int u = 0; u < 3; u++)
                #pragma unroll
                for (int vv = 0; vv < 3; vv++) {
                    const float* wp = &wsm[(ic * 9 + u * 3 + vv) * OCB];
                    #pragma unroll
                    for (int o = 0; o < OCB; o++) {
                        float wv = wp[o];
                        #pragma unroll
                        for (int k = 0; k < 4; k++)
                            acc[o][k] += v[u + k][vv] * wv;
                    }
                }
            inb += IH * IW;
        }

        // optional 1x1 bypass (EPI 3)
        float bp[OCB][4];
        if (EPI == 3) {
            #pragma unroll
            for (int o = 0; o < OCB; o++)
                #pragma unroll
                for (int k = 0; k < 4; k++) bp[o][k] = 0.f;
            for (int c = 0; c < 64; c++) {
                float wv[OCB];
                #pragma unroll
                for (int o = 0; o < OCB; o++)
                    wv[o] = __ldg(wb + (ocblk * OCB + o) * 64 + c);
                #pragma unroll
                for (int k = 0; k < 4; k++) {
                    int row = row0 + k;
                    if (row < OH) {
                        float xv = __ldg(aux2 + (((size_t)n * 64 + c) * 32 + row) * 32 + col);
                        #pragma unroll
                        for (int o = 0; o < OCB; o++) bp[o][k] += xv * wv[o];
                    }
                }
            }
        }

        #pragma unroll
        for (int o = 0; o < OCB; o++) {
            int og = ocblk * OCB + o;
            #pragma unroll
            for (int k = 0; k < 4; k++) {
                int row = row0 + k;
                if (row < row_base0 + ROWS && row < OH) {
                    size_t oidx = (((size_t)n * OC + og) * OH + row) * OW + col;
                    float val = acc[o][k];
                    if (EPI == 1) val = fmaxf(val, 0.f);
                    else if (EPI == 2) val = aux[oidx] - val;
                    else if (EPI == 3) val = aux[oidx] + val + bp[o][k];
                    out[oidx] = val;
                }
            }
        }
    }
}

// 10 pairwise dot products of {m0,m1,m2,m3}; deterministic two-stage reduce.
__global__ __launch_bounds__(256)
void dots_kernel(const float* __restrict__ m0, const float* __restrict__ m1,
                 const float* __restrict__ m2, const float* __restrict__ m3,
                 double* __restrict__ partials)
{
    double loc[10];
    #pragma unroll
    for (int d = 0; d < 10; d++) loc[d] = 0.0;
    for (int i = blockIdx.x * blockDim.x + threadIdx.x; i < NRES;
         i += gridDim.x * blockDim.x) {
        double a = m0[i], b = m1[i], c = m2[i], d = m3[i];
        loc[0] += a * a; loc[1] += a * b; loc[2] += a * c; loc[3] += a * d;
        loc[4] += b * b; loc[5] += b * c; loc[6] += b * d;
        loc[7] += c * c; loc[8] += c * d; loc[9] += d * d;
    }
    __shared__ double sm[256];
    for (int d = 0; d < 10; d++) {
        sm[threadIdx.x] = loc[d];
        __syncthreads();
        for (int s = 128; s > 0; s >>= 1) {
            if (threadIdx.x < s) sm[threadIdx.x] += sm[threadIdx.x + s];
            __syncthreads();
        }
        if (threadIdx.x == 0) partials[blockIdx.x * 10 + d] = sm[0];
        __syncthreads();
    }
}

// Final reduce of partials + 500-step scalar recursion in the Krylov basis.
__global__ void recur_kernel(const double* __restrict__ partials,
                             float* __restrict__ wout)
{
    if (threadIdx.x != 0) return;
    double dots[10];
    for (int d = 0; d < 10; d++) {
        double s = 0.0;
        for (int b = 0; b < NDOTCTA; b++) s += partials[b * 10 + d];
        dots[d] = s;
    }
    double H[4][4];
    H[0][0] = dots[0]; H[0][1] = H[1][0] = dots[1];
    H[0][2] = H[2][0] = dots[2]; H[0][3] = H[3][0] = dots[3];
    H[1][1] = dots[4]; H[1][2] = H[2][1] = dots[5];
    H[1][3] = H[3][1] = dots[6];
    H[2][2] = dots[7]; H[2][3] = H[3][2] = dots[8];
    H[3][3] = dots[9];

    double p[4] = {1.0, 0.0, 0.0, 0.0};
    double w[4] = {0.0, 0.0, 0.0, 0.0};
    for (int t = 0; t < 500; t++) {
        double nsq = 0.0;
        for (int i = 0; i < 4; i++)
            for (int j = 0; j < 4; j++) nsq += p[i] * H[i][j] * p[j];
        double c = LRD / sqrt(nsq);
        for (int i = 0; i < 4; i++) w[i] += c * p[i];
        // r <- r - c * M r ; M shifts basis index up by one (m4 term ~1e-9, dropped)
        p[3] -= c * p[2];
        p[2] -= c * p[1];
        p[1] -= c * p[0];
    }
    for (int i = 0; i < 4; i++) wout[i] = (float)w[i];
}

// s = w0*m0 + w1*m1 + w2*m2 + w3*m3
__global__ __launch_bounds__(256)
void combine_kernel(const float* __restrict__ m0, const float* __restrict__ m1,
                    const float* __restrict__ m2, const float* __restrict__ m3,
                    const float* __restrict__ w, float* __restrict__ s)
{
    float w0 = __ldg(w), w1 = __ldg(w + 1), w2 = __ldg(w + 2), w3 = __ldg(w + 3);
    for (int i = blockIdx.x * blockDim.x + threadIdx.x; i < NRES;
         i += gridDim.x * blockDim.x)
        s[i] = w0 * m0[i] + w1 * m1[i] + w2 * m2[i] + w3 * m3[i];
}

extern "C" void kernel_launch(void* const* d_in, const int* in_sizes, int n_in,
                              void* d_out, int out_size)
{
    const float* x   = (const float*)d_in[0];
    const float* Wff = (const float*)d_in[1];
    const float* Wfb = (const float*)d_in[2];
    const float* Wbp = (const float*)d_in[3];
    float* out = (float*)d_out;

    float *y0, *r0, *t, *m1, *m2, *m3, *s, *w;
    double* part;
    cudaGetSymbolAddress((void**)&y0, g_y0);
    cudaGetSymbolAddress((void**)&r0, g_r0);
    cudaGetSymbolAddress((void**)&t,  g_t);
    cudaGetSymbolAddress((void**)&m1, g_m1);
    cudaGetSymbolAddress((void**)&m2, g_m2);
    cudaGetSymbolAddress((void**)&m3, g_m3);
    cudaGetSymbolAddress((void**)&s,  g_s);
    cudaGetSymbolAddress((void**)&w,  g_w);
    cudaGetSymbolAddress((void**)&part, g_part);

    // y0 = relu(conv3x3_pad1(x, W_ff))                       (64 -> 128)
    conv3<64,128,32,32,32,32,-1,0,1,4,1,256>
        <<<dim3(32,4,1),256>>>(x, Wff, nullptr, nullptr, nullptr, y0);
    // r0 = x - A(pad(y0)) : corr3x3 pad1 over y0, transposed W_fb  (128 -> 64)
    conv3<128,64,32,32,32,32,-1,1,2,4,2,128>
        <<<dim3(16,4,2),128>>>(y0, Wfb, x, nullptr, nullptr, r0);

    // m1 = M r0 = A(A^T r0)
    conv3<64,128,32,32,34,34,-2,2,0,4,1,256>
        <<<dim3(32,4,1),256>>>(r0, Wfb, nullptr, nullptr, nullptr, t);
    conv3<128,64,34,34,32,32, 0,1,0,4,2,128>
        <<<dim3(16,4,2),128>>>(t, Wfb, nullptr, nullptr, nullptr, m1);
    // m2 = M m1
    conv3<64,128,32,32,34,34,-2,2,0,4,1,256>
        <<<dim3(32,4,1),256>>>(m1, Wfb, nullptr, nullptr, nullptr, t);
    conv3<128,64,34,34,32,32, 0,1,0,4,2,128>
        <<<dim3(16,4,2),128>>>(t, Wfb, nullptr, nullptr, nullptr, m2);
    // m3 = M m2
    conv3<64,128,32,32,34,34,-2,2,0,4,1,256>
        <<<dim3(32,4,1),256>>>(m2, Wfb, nullptr, nullptr, nullptr, t);
    conv3<128,64,34,34,32,32, 0,1,0,4,2,128>
        <<<dim3(16,4,2),128>>>(t, Wfb, nullptr, nullptr, nullptr, m3);

    // Gram matrix, scalar 500-step recursion, s = sum w_i m_i
    dots_kernel<<<NDOTCTA,256>>>(r0, m1, m2, m3, part);
    recur_kernel<<<1,32>>>(part, w);
    combine_kernel<<<256,256>>>(r0, m1, m2, m3, w, s);

    // out = y0 + crop(A^T s) + conv1x1(x, W_bypass)
    conv3<64,128,32,32,32,32,-1,2,3,4,1,256>
        <<<dim3(32,4,1),256>>>(s, Wfb, y0, x, Wbp, out);
}

// round 2
// speedup vs baseline: 4.9493x; 4.9493x over previous
#include <cuda_runtime.h>
#include <math.h>

// Problem constants
constexpr int Bn = 4;
constexpr float LRF = 0.001f;

// Padded buffer sizes
constexpr int NY0 = 4 * 128 * 34 * 34;   // y0 padded (pad 1)
constexpr int NRP = 4 * 64 * 36 * 36;    // r-space padded (pad 2)
constexpr int NDOTCTA = 128;

// Scratch (static device arrays: no allocation allowed)
__device__ float g_y0[NY0];
__device__ float g_r0[NRP];
__device__ float g_m1[NRP];
__device__ float g_m2[NRP];
__device__ float g_m3[NRP];
__device__ float g_s[NRP];
__device__ float g_T[64 * 64 * 25];
__device__ double g_part[NDOTCTA * 10];
__device__ float g_w[4];

// ---------------------------------------------------------------------------
// Zero all padded scratch buffers (borders must be 0 each launch).
// ---------------------------------------------------------------------------
__global__ __launch_bounds__(256) void zero_all()
{
    int i = blockIdx.x * blockDim.x + threadIdx.x;
    int stride = gridDim.x * blockDim.x;
    for (int j = i; j < NY0; j += stride) g_y0[j] = 0.f;
    for (int j = i; j < NRP; j += stride) {
        g_r0[j] = 0.f; g_m1[j] = 0.f; g_m2[j] = 0.f; g_m3[j] = 0.f; g_s[j] = 0.f;
    }
}

// ---------------------------------------------------------------------------
// Generic 3x3 conv (cross-correlation), logical 32x32 output.
// Input buffer dims IIHxIIW with logical (r,c) at buffer (r+IPAD, c+IPAD).
// Output buffer dims OPHxOPW with logical (r,c) at (r+OPAD, c+OPAD).
// WM: 0 -> wgt[og][ic][u][v]; 1 -> wgt[ic][og][u][v]; 2 -> wgt[og][ic][2-u][2-v]
// EPI: 1 -> relu(acc); 2 -> x[logical] - acc; 3 -> y0pad[logical] + acc + 1x1(x,wb)
// BOUNDS: predicate input reads against logical [0,32) (only for raw x input).
// Thread: col = tid%32, strip = tid/32 (4 strips x 4 rows = 16 rows);
// grid = (OC/OCB, B, 2).
// ---------------------------------------------------------------------------
template<int IC, int OC, int IIH, int IIW, int IPAD, int OFF, int WM, int EPI,
         int OPAD, int OPH, int OPW, bool BOUNDS, int OCB, int THREADS>
__global__ __launch_bounds__(THREADS)
void conv3(const float* __restrict__ in, const float* __restrict__ wgt,
           const float* __restrict__ aux, const float* __restrict__ aux2,
           const float* __restrict__ wb, float* __restrict__ out)
{
    __shared__ float wsm[OCB * IC * 9];
    __shared__ float wbs[(EPI == 3) ? 64 * OCB : 1];

    const int ocblk = blockIdx.x;
    const int n     = blockIdx.y;
    const int tid   = threadIdx.x;

    for (int idx = tid; idx < OCB * IC * 9; idx += THREADS) {
        int o  = idx % OCB;
        int uv = (idx / OCB) % 9;
        int ic = idx / (9 * OCB);
        int u = uv / 3, v = uv % 3;
        int og = ocblk * OCB + o;
        int src;
        if (WM == 0)      src = ((og * IC + ic) * 3 + u) * 3 + v;
        else if (WM == 1) src = ((ic * OC + og) * 3 + u) * 3 + v;
        else              src = ((og * IC + ic) * 3 + (2 - u)) * 3 + (2 - v);
        wsm[idx] = wgt[src];
    }
    if (EPI == 3) {
        for (int idx = tid; idx < 64 * OCB; idx += THREADS) {
            int o = idx % OCB, c = idx / OCB;
            wbs[idx] = wb[(ocblk * OCB + o) * 64 + c];
        }
    }
    __syncthreads();

    const int col  = tid & 31;
    const int row0 = blockIdx.z * 16 + (tid >> 5) * 4;

    float acc[OCB][4];
    #pragma unroll
    for (int o = 0; o < OCB; o++)
        #pragma unroll
        for (int k = 0; k < 4; k++) acc[o][k] = 0.f;

    int  rix[6], cix[3];
    bool rok[6], cok[3];
    #pragma unroll
    for (int rr = 0; rr < 6; rr++) {
        int r = row0 + OFF + rr;           // logical
        if (BOUNDS) { rok[rr] = (r >= 0 && r < 32); rix[rr] = (rok[rr] ? r : 0) * IIW; }
        else        { rok[rr] = true;      rix[rr] = (r + IPAD) * IIW; }
    }
    #pragma unroll
    for (int cc = 0; cc < 3; cc++) {
        int c = col + OFF + cc;
        if (BOUNDS) { cok[cc] = (c >= 0 && c < 32); cix[cc] = cok[cc] ? c : 0; }
        else        { cok[cc] = true;      cix[cc] = c + IPAD; }
    }

    const float* inb = in + (size_t)n * IC * IIH * IIW;
    #pragma unroll 2
    for (int ic = 0; ic < IC; ic++) {
        float v[6][3];
        #pragma unroll
        for (int rr = 0; rr < 6; rr++)
            #pragma unroll
            for (int cc = 0; cc < 3; cc++) {
                if (BOUNDS)
                    v[rr][cc] = (rok[rr] && cok[cc]) ? __ldg(inb + rix[rr] + cix[cc]) : 0.f;
                else
                    v[rr][cc] = __ldg(inb + rix[rr] + cix[cc]);
            }
        #pragma unroll
        for (int u = 0; u < 3; u++)
            #pragma unroll
            for (int vv = 0; vv < 3; vv++) {
                const float* wp = &wsm[(ic * 9 + u * 3 + vv) * OCB];
                #pragma unroll
                for (int o = 0; o < OCB; o++) {
                    float wv = wp[o];
                    #pragma unroll
                    for (int k = 0; k < 4; k++)
                        acc[o][k] += v[u + k][vv] * wv;
                }
            }
        inb += IIH * IIW;
    }

    // 1x1 bypass for EPI==3
    float bp[OCB][4];
    if (EPI == 3) {
        #pragma unroll
        for (int o = 0; o < OCB; o++)
            #pragma unroll
            for (int k = 0; k < 4; k++) bp[o][k] = 0.f;
        const float* xb = aux2 + ((size_t)n * 64 * 32 + row0) * 32 + col;
        #pragma unroll 4
        for (int c = 0; c < 64; c++) {
            float xv[4];
            #pragma unroll
            for (int k = 0; k < 4; k++) xv[k] = __ldg(xb + k * 32);
            #pragma unroll
            for (int o = 0; o < OCB; o++) {
                float wv = wbs[c * OCB + o];
                #pragma unroll
                for (int k = 0; k < 4; k++) bp[o][k] += xv[k] * wv;
            }
            xb += 32 * 32;
        }
    }

    #pragma unroll
    for (int o = 0; o < OCB; o++) {
        int og = ocblk * OCB + o;
        #pragma unroll
        for (int k = 0; k < 4; k++) {
            int row = row0 + k;
            float val = acc[o][k];
            if (EPI == 1) val = fmaxf(val, 0.f);
            else if (EPI == 2)
                val = __ldg(aux + (((size_t)n * OC + og) * 32 + row) * 32 + col) - val;
            else if (EPI == 3)
                val = __ldg(aux + (((size_t)n * 128 + og) * 34 + row + 1) * 34 + col + 1)
                      + val + bp[o][k];
            size_t oidx = (((size_t)n * OC + og) * OPH + row + OPAD) * OPW + col + OPAD;
            out[oidx] = val;
        }
    }
}

// ---------------------------------------------------------------------------
// Gram kernel: T[b][a][du+2][dv+2] = sum_o sum_{u,v} Wfb[o][b][u][v]*Wfb[o][a][u-du][v-dv]
// grid = 64 (b), block = 128 (a x o-half).
// ---------------------------------------------------------------------------
__global__ __launch_bounds__(128)
void tgram_kernel(const float* __restrict__ Wfb, float* __restrict__ T)
{
    __shared__ float red[64 * 25];
    const int b    = blockIdx.x;
    const int a    = threadIdx.x & 63;
    const int half = threadIdx.x >> 6;

    float acc[25];
    #pragma unroll
    for (int t = 0; t < 25; t++) acc[t] = 0.f;

    for (int o = half * 64; o < half * 64 + 64; o++) {
        float wbv[9], wav[9];
        #pragma unroll
        for (int i = 0; i < 9; i++) {
            wbv[i] = __ldg(Wfb + (o * 64 + b) * 9 + i);
            wav[i] = __ldg(Wfb + (o * 64 + a) * 9 + i);
        }
        #pragma unroll
        for (int du = -2; du <= 2; du++)
            #pragma unroll
            for (int dv = -2; dv <= 2; dv++) {
                float s = 0.f;
                #pragma unroll
                for (int u = 0; u < 3; u++) {
                    if (u - du < 0 || u - du > 2) continue;
                    #pragma unroll
                    for (int v = 0; v < 3; v++) {
                        if (v - dv < 0 || v - dv > 2) continue;
                        s += wbv[u * 3 + v] * wav[(u - du) * 3 + (v - dv)];
                    }
                }
                acc[(du + 2) * 5 + (dv + 2)] += s;
            }
    }
    if (half == 1) {
        #pragma unroll
        for (int t = 0; t < 25; t++) red[a * 25 + t] = acc[t];
    }
    __syncthreads();
    if (half == 0) {
        #pragma unroll
        for (int t = 0; t < 25; t++)
            T[((size_t)b * 64 + a) * 25 + t] = acc[t] + red[a * 25 + t];
    }
}

// ---------------------------------------------------------------------------
// 5x5 conv in r-space (M = A A^T), padded 36x36 buffers, 64->64 channels.
// grid = (32, 4, 2), block 128; OCB = 2.
// ---------------------------------------------------------------------------
__global__ __launch_bounds__(128)
void conv5_kernel(const float* __restrict__ in, const float* __restrict__ T,
                  float* __restrict__ out)
{
    constexpr int OCB = 2;
    __shared__ float wsm[64 * 25 * OCB];

    const int ocblk = blockIdx.x;
    const int n     = blockIdx.y;
    const int tid   = threadIdx.x;

    for (int idx = tid; idx < 64 * 25 * OCB; idx += 128) {
        int o   = idx % OCB;
        int tap = (idx / OCB) % 25;
        int a   = idx / (25 * OCB);
        wsm[idx] = __ldg(T + ((size_t)(ocblk * OCB + o) * 64 + a) * 25 + tap);
    }
    __syncthreads();

    const int col  = tid & 31;
    const int row0 = blockIdx.z * 16 + (tid >> 5) * 4;

    float acc[OCB][4];
    #pragma unroll
    for (int o = 0; o < OCB; o++)
        #pragma unroll
        for (int k = 0; k < 4; k++) acc[o][k] = 0.f;

    const float* inb = in + (((size_t)n * 64) * 36 + row0) * 36 + col;
    for (int a = 0; a < 64; a++) {
        float v[8][5];
        #pragma unroll
        for (int rr = 0; rr < 8; rr++)
            #pragma unroll
            for (int cc = 0; cc < 5; cc++)
                v[rr][cc] = __ldg(inb + rr * 36 + cc);
        #pragma unroll
        for (int du = 0; du < 5; du++)
            #pragma unroll
            for (int dv = 0; dv < 5; dv++) {
                const float* wp = &wsm[(a * 25 + du * 5 + dv) * OCB];
                #pragma unroll
                for (int o = 0; o < OCB; o++) {
                    float wv = wp[o];
                    #pragma unroll
                    for (int k = 0; k < 4; k++)
                        acc[o][k] += v[k + du][dv] * wv;
                }
            }
        inb += 36 * 36;
    }

    #pragma unroll
    for (int o = 0; o < OCB; o++) {
        int og = ocblk * OCB + o;
        #pragma unroll
        for (int k = 0; k < 4; k++)
            out[(((size_t)n * 64 + og) * 36 + row0 + k + 2) * 36 + col + 2] = acc[o][k];
    }
}

// ---------------------------------------------------------------------------
// 10 pairwise dot products over padded arrays (borders are zero everywhere).
// ---------------------------------------------------------------------------
__global__ __launch_bounds__(256)
void dots_kernel(const float* __restrict__ m0, const float* __restrict__ m1,
                 const float* __restrict__ m2, const float* __restrict__ m3,
                 double* __restrict__ partials)
{
    double loc[10];
    #pragma unroll
    for (int d = 0; d < 10; d++) loc[d] = 0.0;
    for (int i = blockIdx.x * blockDim.x + threadIdx.x; i < NRP;
         i += gridDim.x * blockDim.x) {
        double a = m0[i], b = m1[i], c = m2[i], d = m3[i];
        loc[0] += a * a; loc[1] += a * b; loc[2] += a * c; loc[3] += a * d;
        loc[4] += b * b; loc[5] += b * c; loc[6] += b * d;
        loc[7] += c * c; loc[8] += c * d; loc[9] += d * d;
    }
    __shared__ double sm[256];
    for (int d = 0; d < 10; d++) {
        sm[threadIdx.x] = loc[d];
        __syncthreads();
        for (int s = 128; s > 0; s >>= 1) {
            if (threadIdx.x < s) sm[threadIdx.x] += sm[threadIdx.x + s];
            __syncthreads();
        }
        if (threadIdx.x == 0) partials[blockIdx.x * 10 + d] = sm[0];
        __syncthreads();
    }
}

// ---------------------------------------------------------------------------
// Final reduce + 500-step scalar recursion in the degree-3 Krylov basis (fp32).
// ---------------------------------------------------------------------------
__global__ void recur_kernel(const double* __restrict__ partials,
                             float* __restrict__ wout)
{
    if (threadIdx.x != 0) return;
    double dots[10];
    for (int d = 0; d < 10; d++) {
        double s = 0.0;
        for (int b = 0; b < NDOTCTA; b++) s += partials[b * 10 + d];
        dots[d] = s;
    }
    const float H00 = (float)dots[0], H01 = (float)dots[1], H02 = (float)dots[2];
    const float H03 = (float)dots[3], H11 = (float)dots[4], H12 = (float)dots[5];
    const float H13 = (float)dots[6], H22 = (float)dots[7], H23 = (float)dots[8];
    const float H33 = (float)dots[9];

    float p1 = 0.f, p2 = 0.f, p3 = 0.f;
    float w0 = 0.f, w1 = 0.f, w2 = 0.f, w3 = 0.f;
    for (int t = 0; t < 500; t++) {
        float nsq = H00
            + 2.f * (p1 * H01 + p2 * H02 + p3 * H03)
            + p1 * (p1 * H11 + 2.f * (p2 * H12 + p3 * H13))
            + p2 * (p2 * H22 + 2.f * p3 * H23)
            + p3 * p3 * H33;
        float c = LRF * rsqrtf(nsq);
        w0 += c; w1 += c * p1; w2 += c * p2; w3 += c * p3;
        p3 -= c * p2;
        p2 -= c * p1;
        p1 -= c;
    }
    wout[0] = w0; wout[1] = w1; wout[2] = w2; wout[3] = w3;
}

// s = w0*m0 + w1*m1 + w2*m2 + w3*m3   (borders stay zero automatically)
__global__ __launch_bounds__(256)
void combine_kernel(const float* __restrict__ m0, const float* __restrict__ m1,
                    const float* __restrict__ m2, const float* __restrict__ m3,
                    const float* __restrict__ w, float* __restrict__ s)
{
    float w0 = __ldg(w), w1 = __ldg(w + 1), w2 = __ldg(w + 2), w3 = __ldg(w + 3);
    for (int i = blockIdx.x * blockDim.x + threadIdx.x; i < NRP;
         i += gridDim.x * blockDim.x)
        s[i] = w0 * m0[i] + w1 * m1[i] + w2 * m2[i] + w3 * m3[i];
}

extern "C" void kernel_launch(void* const* d_in, const int* in_sizes, int n_in,
                              void* d_out, int out_size)
{
    const float* x   = (const float*)d_in[0];
    const float* Wff = (const float*)d_in[1];
    const float* Wfb = (const float*)d_in[2];
    const float* Wbp = (const float*)d_in[3];
    float* out = (float*)d_out;

    float *y0, *r0, *m1, *m2, *m3, *s, *w, *T;
    double* part;
    cudaGetSymbolAddress((void**)&y0, g_y0);
    cudaGetSymbolAddress((void**)&r0, g_r0);
    cudaGetSymbolAddress((void**)&m1, g_m1);
    cudaGetSymbolAddress((void**)&m2, g_m2);
    cudaGetSymbolAddress((void**)&m3, g_m3);
    cudaGetSymbolAddress((void**)&s,  g_s);
    cudaGetSymbolAddress((void**)&w,  g_w);
    cudaGetSymbolAddress((void**)&T,  g_T);
    cudaGetSymbolAddress((void**)&part, g_part);

    dim3 cgrid(32, 4, 2);

    zero_all<<<512, 256>>>();

    // y0 = relu(conv3x3_pad1(x, W_ff)) -> padded (4,128,34,34)
    conv3<64, 128, 32, 32, 0, -1, 0, 1, 1, 34, 34, true, 4, 128>
        <<<cgrid, 128>>>(x, Wff, nullptr, nullptr, nullptr, y0);

    // Gram kernel for M = A A^T (independent of y0; any order)
    tgram_kernel<<<64, 128>>>(Wfb, T);

    // r0 = x - A(pad(y0)) -> padded (4,64,36,36)
    conv3<128, 64, 34, 34, 1, -1, 1, 2, 2, 36, 36, false, 2, 128>
        <<<cgrid, 128>>>(y0, Wfb, x, nullptr, nullptr, r0);

    // m_{i+1} = M m_i via single 5x5 conv per application
    conv5_kernel<<<cgrid, 128>>>(r0, T, m1);
    conv5_kernel<<<cgrid, 128>>>(m1, T, m2);
    conv5_kernel<<<cgrid, 128>>>(m2, T, m3);

    // Gram matrix of Krylov basis, scalar 500-step recursion, combine
    dots_kernel<<<NDOTCTA, 256>>>(r0, m1, m2, m3, part);
    recur_kernel<<<1, 32>>>(part, w);
    combine_kernel<<<256, 256>>>(r0, m1, m2, m3, w, s);

    // out = y0 + crop(A^T s) + conv1x1(x, W_bypass)
    conv3<64, 128, 36, 36, 2, -1, 2, 3, 0, 32, 32, false, 4, 128>
        <<<cgrid, 128>>>(s, Wfb, y0, x, Wbp, out);
}